// round 1
// baseline (speedup 1.0000x reference)
#include <cuda_runtime.h>

#define TT 256
#define BB 64
#define DD 1024
#define HH 1024
#define G4 4096
#define EPSF 0.01f

// ---------------- device scratch (static: allocation-free kernel_launch) ---
static __device__ float g_G[(size_t)TT * BB * G4];     // x@W_ih.T + b_ih + b_hh   (256 MB)
static __device__ float g_xn2[TT * BB];                // |x_t|^2 per (t,b)
static __device__ float g_hn2[(TT + 1) * BB];          // |h_t|^2 per (t,b), accumulated
static __device__ float g_h[2][BB * HH];               // ping-pong hidden
static __device__ float g_dh[2][BB * HH];              // ping-pong tangent hidden
static __device__ float g_c[BB * HH];
static __device__ float g_dc[BB * HH];

// ---------------- init: zero states & norm accumulators (runs every replay) --
__global__ void init_kernel() {
    int idx = blockIdx.x * blockDim.x + threadIdx.x;
    int stride = gridDim.x * blockDim.x;
    for (int i = idx; i < BB * HH; i += stride) {
        g_h[0][i] = 0.f; g_h[1][i] = 0.f;
        g_dh[0][i] = 0.f; g_dh[1][i] = 0.f;
        g_c[i] = 0.f; g_dc[i] = 0.f;
    }
    for (int i = idx; i < (TT + 1) * BB; i += stride) g_hn2[i] = 0.f;
}

// ---------------- |x_t|^2 ---------------------------------------------------
__global__ void xnorm_kernel(const float* __restrict__ x) {
    int row = blockIdx.x;                 // t*BB + b
    const float* xr = x + (size_t)row * DD;
    float s = 0.f;
    for (int i = threadIdx.x; i < DD; i += blockDim.x) { float v = xr[i]; s += v * v; }
    __shared__ float red[8];
    #pragma unroll
    for (int o = 16; o > 0; o >>= 1) s += __shfl_xor_sync(0xffffffffu, s, o);
    if ((threadIdx.x & 31) == 0) red[threadIdx.x >> 5] = s;
    __syncthreads();
    if (threadIdx.x < 8) {
        s = red[threadIdx.x];
        #pragma unroll
        for (int o = 4; o > 0; o >>= 1) s += __shfl_xor_sync(0xffu, s, o);
        if (threadIdx.x == 0) g_xn2[row] = s;
    }
}

// ---------------- precompute GEMM: G = x @ W_ih.T + (b_ih + b_hh) -----------
// M=16384, N=4096, K=1024. 128x128 tile, BK=8, 256 threads, 8x8 micro.
__global__ void __launch_bounds__(256) pre_gemm(const float* __restrict__ x,
                                                const float* __restrict__ Wih,
                                                const float* __restrict__ bih,
                                                const float* __restrict__ bhh) {
    __shared__ __align__(16) float As[128 * 12];   // [m][k] pad 12
    __shared__ __align__(16) float Bs[8 * 132];    // [k][n] pad 132
    const int n0 = blockIdx.x * 128;
    const int m0 = blockIdx.y * 128;
    const int tid = threadIdx.x;
    const int tx = tid & 15, ty = tid >> 4;        // 16x16 thread grid
    const int lrow = tid >> 1, lhalf = tid & 1;

    float acc[8][8];
    #pragma unroll
    for (int i = 0; i < 8; i++)
        #pragma unroll
        for (int j = 0; j < 8; j++) acc[i][j] = 0.f;

    const float* aptr = x   + (size_t)(m0 + lrow) * DD + lhalf * 4;
    const float* bptr = Wih + (size_t)(n0 + lrow) * DD + lhalf * 4;

    for (int k0 = 0; k0 < DD; k0 += 8) {
        float4 av = *(const float4*)(aptr + k0);
        float4 bv = *(const float4*)(bptr + k0);
        *(float4*)(As + lrow * 12 + lhalf * 4) = av;
        Bs[(lhalf * 4 + 0) * 132 + lrow] = bv.x;
        Bs[(lhalf * 4 + 1) * 132 + lrow] = bv.y;
        Bs[(lhalf * 4 + 2) * 132 + lrow] = bv.z;
        Bs[(lhalf * 4 + 3) * 132 + lrow] = bv.w;
        __syncthreads();
        #pragma unroll
        for (int kq = 0; kq < 2; kq++) {
            float4 a[8];
            #pragma unroll
            for (int i = 0; i < 8; i++)
                a[i] = *(const float4*)(As + (8 * ty + i) * 12 + kq * 4);
            float4 b0[4], b1[4];
            #pragma unroll
            for (int e = 0; e < 4; e++) {
                b0[e] = *(const float4*)(Bs + (kq * 4 + e) * 132 + 8 * tx);
                b1[e] = *(const float4*)(Bs + (kq * 4 + e) * 132 + 8 * tx + 4);
            }
            #pragma unroll
            for (int i = 0; i < 8; i++) {
                const float* ai = reinterpret_cast<const float*>(&a[i]);
                #pragma unroll
                for (int e = 0; e < 4; e++) {
                    const float* p0 = reinterpret_cast<const float*>(&b0[e]);
                    const float* p1 = reinterpret_cast<const float*>(&b1[e]);
                    float av_ = ai[e];
                    #pragma unroll
                    for (int j = 0; j < 4; j++) {
                        acc[i][j]     += av_ * p0[j];
                        acc[i][4 + j] += av_ * p1[j];
                    }
                }
            }
        }
        __syncthreads();
    }

    float bsum[8];
    #pragma unroll
    for (int j = 0; j < 8; j++) {
        int n = n0 + 8 * tx + j;
        bsum[j] = bih[n] + bhh[n];
    }
    #pragma unroll
    for (int i = 0; i < 8; i++) {
        size_t row = (size_t)(m0 + 8 * ty + i);
        float* dst = g_G + row * G4 + n0 + 8 * tx;
        float4 o0, o1;
        o0.x = acc[i][0] + bsum[0]; o0.y = acc[i][1] + bsum[1];
        o0.z = acc[i][2] + bsum[2]; o0.w = acc[i][3] + bsum[3];
        o1.x = acc[i][4] + bsum[4]; o1.y = acc[i][5] + bsum[5];
        o1.z = acc[i][6] + bsum[6]; o1.w = acc[i][7] + bsum[7];
        *(float4*)dst       = o0;
        *(float4*)(dst + 4) = o1;
    }
}

// ---------------- per-step fused kernel --------------------------------------
// Grid 128 CTAs x 128 threads. CTA owns 8 h-columns (n0..n0+7) across all 4
// gates -> 32 W_hh rows. GEMM A = [h(64); dh(64)] (128 x 1024), output 128x32,
// then fused LSTM+MAGE elementwise update for those columns.
__global__ void __launch_bounds__(128) step_kernel(int t, const float* __restrict__ g,
                                                   const float* __restrict__ Whh,
                                                   float* __restrict__ out) {
    __shared__ __align__(16) float As[128 * 36];   // GEMM A tile; later pre_s[128][33]
    __shared__ __align__(16) float Ws[32 * 36];    // W tile [r][k]
    const int n0 = blockIdx.x * 8;
    const int tid = threadIdx.x;
    const int tx = tid & 7, ty = tid >> 3;         // tx<8 (cols/4), ty<16 (rows/8)
    const float* hprev  = g_h[t & 1];
    const float* dhprev = g_dh[t & 1];

    float acc[8][4];
    #pragma unroll
    for (int i = 0; i < 8; i++)
        #pragma unroll
        for (int j = 0; j < 4; j++) acc[i][j] = 0.f;

    for (int k0 = 0; k0 < HH; k0 += 32) {
        // load A tile: 128 rows x 32 k (h rows 0-63, dh rows 64-127)
        #pragma unroll
        for (int l = 0; l < 8; l++) {
            int fl = tid + l * 128;
            int m = fl >> 3, f4 = (fl & 7) << 2;
            const float* src = (m < BB) ? (hprev + m * HH) : (dhprev + (m - BB) * HH);
            *(float4*)(As + m * 36 + f4) = *(const float4*)(src + k0 + f4);
        }
        // load W tile: 32 rows (4 gates x 8 cols) x 32 k
        #pragma unroll
        for (int l = 0; l < 2; l++) {
            int fl = tid + l * 128;
            int r = fl >> 3, f4 = (fl & 7) << 2;
            int q = r >> 3, j = r & 7;
            const float* src = Whh + ((size_t)q * HH + n0 + j) * HH;
            *(float4*)(Ws + r * 36 + f4) = *(const float4*)(src + k0 + f4);
        }
        __syncthreads();
        #pragma unroll
        for (int kq = 0; kq < 8; kq++) {
            float4 a[8], w[4];
            #pragma unroll
            for (int i = 0; i < 8; i++)
                a[i] = *(const float4*)(As + (8 * ty + i) * 36 + kq * 4);
            #pragma unroll
            for (int j = 0; j < 4; j++)
                w[j] = *(const float4*)(Ws + (4 * tx + j) * 36 + kq * 4);
            #pragma unroll
            for (int i = 0; i < 8; i++)
                #pragma unroll
                for (int j = 0; j < 4; j++)
                    acc[i][j] += a[i].x * w[j].x + a[i].y * w[j].y
                               + a[i].z * w[j].z + a[i].w * w[j].w;
        }
        __syncthreads();
    }

    // stash pre-activations to smem (rows 0-63 primal, 64-127 tangent)
    #pragma unroll
    for (int i = 0; i < 8; i++)
        #pragma unroll
        for (int j = 0; j < 4; j++)
            As[(8 * ty + i) * 33 + 4 * tx + j] = acc[i][j];
    __syncthreads();

    float* hnext  = g_h[(t + 1) & 1];
    float* dhnext = g_dh[(t + 1) & 1];

    #pragma unroll
    for (int it = 0; it < 4; it++) {
        int item = tid + it * 128;          // [0,512): (b, jj)
        int b = item >> 3, jj = item & 7;
        int col = n0 + jj;
        size_t gbase = ((size_t)t * BB + b) * G4 + col;

        float pi = As[b * 33 + jj]       + g_G[gbase];
        float pf = As[b * 33 + 8 + jj]   + g_G[gbase + HH];
        float pg = As[b * 33 + 16 + jj]  + g_G[gbase + 2 * HH];
        float po = As[b * 33 + 24 + jj]  + g_G[gbase + 3 * HH];
        float dhi = As[(64 + b) * 33 + jj];
        float dhf = As[(64 + b) * 33 + 8 + jj];
        float dhg = As[(64 + b) * 33 + 16 + jj];
        float dho = As[(64 + b) * 33 + 24 + jj];

        float g0 = EPSF * g[gbase];
        float g1 = EPSF * g[gbase + HH];
        float g2 = EPSF * g[gbase + 2 * HH];
        float g3 = EPSF * g[gbase + 3 * HH];

        float n2  = g_xn2[t * BB + b] + g_hn2[t * BB + b] + 2.0f;
        float nrm = sqrtf(n2);
        float inv = 1.0f / nrm;
        float s   = (n2 - 2.0f) * inv;

        float iv = 1.0f / (1.0f + expf(-pi));
        float fv = 1.0f / (1.0f + expf(-pf));
        float gv = tanhf(pg);
        float ov = 1.0f / (1.0f + expf(-po));

        float dpi = g0 * (s + inv) + g1 * inv + dhi;
        float dpf = g1 * s + (g2 + g3) * inv + dhf;
        float dpg = g2 * s + (g0 + g1) * inv + dhg;
        float dpo = g3 * s + (g2 + g3) * inv + dho;

        float di  = iv * (1.f - iv) * dpi;
        float df  = fv * (1.f - fv) * dpf;
        float dg  = (1.f - gv * gv) * dpg;
        float dov = ov * (1.f - ov) * dpo;

        int sidx = b * HH + col;
        float c = g_c[sidx], dc = g_dc[sidx];
        float c2  = fv * c + iv * gv;
        float dc2 = df * c + fv * dc + di * gv + iv * dg;
        float tc  = tanhf(c2);
        float h2  = ov * tc;
        float dh2 = dov * tc + ov * (1.f - tc * tc) * dc2;

        g_c[sidx] = c2;  g_dc[sidx] = dc2;
        hnext[sidx] = h2; dhnext[sidx] = dh2;

        size_t obase = ((size_t)t * BB + b) * HH + col;
        out[obase] = h2;
        out[(size_t)TT * BB * HH + obase] = dh2;

        atomicAdd(&g_hn2[(t + 1) * BB + b], h2 * h2);
    }
}

// ---------------- launch ------------------------------------------------------
extern "C" void kernel_launch(void* const* d_in, const int* in_sizes, int n_in,
                              void* d_out, int out_size) {
    const float* x   = (const float*)d_in[0];   // [T,B,D]
    const float* g   = (const float*)d_in[1];   // [T,B,4H]
    const float* Wih = (const float*)d_in[2];   // [4H,D]
    const float* Whh = (const float*)d_in[3];   // [4H,H]
    const float* bih = (const float*)d_in[4];   // [4H]
    const float* bhh = (const float*)d_in[5];   // [4H]
    float* out = (float*)d_out;                 // [2,T,B,H]

    init_kernel<<<256, 256>>>();
    xnorm_kernel<<<TT * BB, 256>>>(x);
    pre_gemm<<<dim3(G4 / 128, (TT * BB) / 128), 256>>>(x, Wih, bih, bhh);
    for (int t = 0; t < TT; t++)
        step_kernel<<<128, 128>>>(t, g, Whh, out);
}